// round 1
// baseline (speedup 1.0000x reference)
#include <cuda_runtime.h>
#include <cstdint>

#define N_USERS 100000
#define N_ITEMS 40000
#define DIM     64
#define NTOT    (N_USERS + N_ITEMS)
#define VPR     (DIM / 4)          // float4 vectors per row = 16

// -------- scratch (allocation-free: __device__ globals) --------
__device__ float4 g_ii1[N_ITEMS * VPR];
__device__ float4 g_uu1[N_USERS * VPR];
__device__ float4 g_ego_a[NTOT * VPR];
__device__ float4 g_ego_b[NTOT * VPR];
__device__ float4 g_acc[NTOT * VPR];

// -------- kernels --------
__global__ __launch_bounds__(256) void k_zero(float4* __restrict__ p, int n) {
    int i = blockIdx.x * blockDim.x + threadIdx.x;
    if (i < n) p[i] = make_float4(0.f, 0.f, 0.f, 0.f);
}

// ego = concat(user, item); acc = ego
__global__ __launch_bounds__(256) void k_init_ego(const float4* __restrict__ u,
                                                  const float4* __restrict__ it,
                                                  float4* __restrict__ ego,
                                                  float4* __restrict__ acc) {
    int i = blockIdx.x * blockDim.x + threadIdx.x;
    if (i >= NTOT * VPR) return;
    float4 v = (i < N_USERS * VPR) ? __ldg(u + i) : __ldg(it + (i - N_USERS * VPR));
    ego[i] = v;
    acc[i] = v;
}

// COO scatter SpMM: y[row] += val * x[col]. 16 threads/edge, float4 lanes,
// vector reduction atomics (red.global.add.v4.f32, sm_90+).
__global__ __launch_bounds__(256) void k_spmm(const int* __restrict__ rows,
                                              const int* __restrict__ cols,
                                              const float* __restrict__ vals,
                                              const float4* __restrict__ x,
                                              float4* __restrict__ y, int nnz) {
    long long t = (long long)blockIdx.x * blockDim.x + threadIdx.x;
    int e = (int)(t >> 4);
    if (e >= nnz) return;
    int c = (int)(t & 15);
    int col = __ldg(cols + e);
    int row = __ldg(rows + e);
    float v  = __ldg(vals + e);
    float4 gx = __ldg(x + (size_t)col * VPR + c);
    float4* addr = y + (size_t)row * VPR + c;
    asm volatile("red.global.add.v4.f32 [%0], {%1,%2,%3,%4};"
                 :: "l"(addr), "f"(gx.x * v), "f"(gx.y * v),
                    "f"(gx.z * v), "f"(gx.w * v)
                 : "memory");
}

// acc += src; optionally zero another buffer (next layer's target) in the same pass
__global__ __launch_bounds__(256) void k_add_zero(float4* __restrict__ acc,
                                                  const float4* __restrict__ src,
                                                  float4* __restrict__ zp, int n) {
    int i = blockIdx.x * blockDim.x + threadIdx.x;
    if (i >= n) return;
    float4 a = acc[i], s = __ldg(src + i);
    acc[i] = make_float4(a.x + s.x, a.y + s.y, a.z + s.z, a.w + s.w);
    if (zp) zp[i] = make_float4(0.f, 0.f, 0.f, 0.f);
}

// out = acc/4 + l2_normalize(g). One warp per row, float2 lanes.
__global__ __launch_bounds__(256) void k_finalize(const float2* __restrict__ acc,
                                                  const float2* __restrict__ g,
                                                  float2* __restrict__ out, int n_rows) {
    int w = (int)((blockIdx.x * (long long)blockDim.x + threadIdx.x) >> 5);
    int lane = threadIdx.x & 31;
    if (w >= n_rows) return;
    size_t idx = (size_t)w * 32 + lane;
    float2 gv = __ldg(g + idx);
    float s = gv.x * gv.x + gv.y * gv.y;
    #pragma unroll
    for (int o = 16; o; o >>= 1) s += __shfl_xor_sync(0xffffffffu, s, o);
    float scale = 1.0f / fmaxf(sqrtf(s), 1e-12f);
    float2 a = __ldg(acc + idx);
    out[idx] = make_float2(a.x * 0.25f + gv.x * scale,
                           a.y * 0.25f + gv.y * scale);
}

// -------- host orchestration --------
static inline int gridFor(long long threads, int tpb) {
    return (int)((threads + tpb - 1) / tpb);
}

extern "C" void kernel_launch(void* const* d_in, const int* in_sizes, int n_in,
                              void* d_out, int out_size) {
    const float4* user_emb = (const float4*)d_in[0];
    const float4* item_emb = (const float4*)d_in[1];
    const float4* uu_emb   = (const float4*)d_in[2];
    const float4* ii_emb   = (const float4*)d_in[3];
    const float*  ui_vals  = (const float*)d_in[4];
    const float*  ii_vals  = (const float*)d_in[5];
    const float*  uu_vals  = (const float*)d_in[6];
    const int*    ui_rows  = (const int*)d_in[7];
    const int*    ui_cols  = (const int*)d_in[8];
    const int*    ii_rows  = (const int*)d_in[9];
    const int*    ii_cols  = (const int*)d_in[10];
    const int*    uu_rows  = (const int*)d_in[11];
    const int*    uu_cols  = (const int*)d_in[12];
    const int nnz_ui = in_sizes[7];
    const int nnz_ii = in_sizes[9];
    const int nnz_uu = in_sizes[11];

    float* out = (float*)d_out;
    float4* out_u  = (float4*)out;                                    // [N_USERS,64]
    float4* out_i  = (float4*)(out + (size_t)N_USERS * DIM);          // [N_ITEMS,64]
    float4* out_ii = (float4*)(out + (size_t)(N_USERS + N_ITEMS) * DIM); // [N_ITEMS,64]
    float4* out_uu = (float4*)(out + (size_t)(N_USERS + 2 * N_ITEMS) * DIM); // [N_USERS,64]

    float4 *p_ii1, *p_uu1, *p_ego_a, *p_ego_b, *p_acc;
    cudaGetSymbolAddress((void**)&p_ii1,   g_ii1);
    cudaGetSymbolAddress((void**)&p_uu1,   g_uu1);
    cudaGetSymbolAddress((void**)&p_ego_a, g_ego_a);
    cudaGetSymbolAddress((void**)&p_ego_b, g_ego_b);
    cudaGetSymbolAddress((void**)&p_acc,   g_acc);

    const int TPB = 256;
    const int nIIv = N_ITEMS * VPR;      // 640k float4
    const int nUUv = N_USERS * VPR;      // 1.6M float4
    const int nEGv = NTOT   * VPR;       // 2.24M float4

    // ---- ii chain (2 layers), final layer scatters straight into d_out ----
    k_zero<<<gridFor(nIIv, TPB), TPB>>>(p_ii1, nIIv);
    k_spmm<<<gridFor((long long)nnz_ii * 16, TPB), TPB>>>(ii_rows, ii_cols, ii_vals,
                                                          ii_emb, p_ii1, nnz_ii);
    k_zero<<<gridFor(nIIv, TPB), TPB>>>(out_ii, nIIv);
    k_spmm<<<gridFor((long long)nnz_ii * 16, TPB), TPB>>>(ii_rows, ii_cols, ii_vals,
                                                          p_ii1, out_ii, nnz_ii);

    // ---- uu chain (2 layers) ----
    k_zero<<<gridFor(nUUv, TPB), TPB>>>(p_uu1, nUUv);
    k_spmm<<<gridFor((long long)nnz_uu * 16, TPB), TPB>>>(uu_rows, uu_cols, uu_vals,
                                                          uu_emb, p_uu1, nnz_uu);
    k_zero<<<gridFor(nUUv, TPB), TPB>>>(out_uu, nUUv);
    k_spmm<<<gridFor((long long)nnz_uu * 16, TPB), TPB>>>(uu_rows, uu_cols, uu_vals,
                                                          p_uu1, out_uu, nnz_uu);

    // ---- ui chain (3 layers with running accumulation) ----
    k_init_ego<<<gridFor(nEGv, TPB), TPB>>>(user_emb, item_emb, p_ego_a, p_acc);
    k_zero<<<gridFor(nEGv, TPB), TPB>>>(p_ego_b, nEGv);
    k_spmm<<<gridFor((long long)nnz_ui * 16, TPB), TPB>>>(ui_rows, ui_cols, ui_vals,
                                                          p_ego_a, p_ego_b, nnz_ui);
    k_add_zero<<<gridFor(nEGv, TPB), TPB>>>(p_acc, p_ego_b, p_ego_a, nEGv);
    k_spmm<<<gridFor((long long)nnz_ui * 16, TPB), TPB>>>(ui_rows, ui_cols, ui_vals,
                                                          p_ego_b, p_ego_a, nnz_ui);
    k_add_zero<<<gridFor(nEGv, TPB), TPB>>>(p_acc, p_ego_a, p_ego_b, nEGv);
    k_spmm<<<gridFor((long long)nnz_ui * 16, TPB), TPB>>>(ui_rows, ui_cols, ui_vals,
                                                          p_ego_a, p_ego_b, nnz_ui);
    k_add_zero<<<gridFor(nEGv, TPB), TPB>>>(p_acc, p_ego_b, (float4*)nullptr, nEGv);

    // ---- finalize: out_u = acc_u/4 + l2n(uu); out_i = acc_i/4 + l2n(ii) ----
    k_finalize<<<gridFor((long long)N_USERS * 32, TPB), TPB>>>(
        (const float2*)p_acc, (const float2*)out_uu, (float2*)out_u, N_USERS);
    k_finalize<<<gridFor((long long)N_ITEMS * 32, TPB), TPB>>>(
        (const float2*)p_acc + (size_t)N_USERS * 32, (const float2*)out_ii,
        (float2*)out_i, N_ITEMS);
}